// round 1
// baseline (speedup 1.0000x reference)
#include <cuda_runtime.h>
#include <math.h>
#include <stdint.h>

#define BB   32
#define SS   512
#define DD   768
#define HH   384
#define G3   (3*HH)      // 1152
#define NROWS (2*G3)     // 2304
#define M16K (SS*BB)     // 16384

// ---------------- scratch (static device globals; no runtime alloc) ----------
__device__ float g_XW[(size_t)NROWS * M16K];        // [n][m], n = dir*1152+gate*384+unit, m = t*32+b
__device__ float g_OUT[(size_t)M16K * (2*HH)];      // [m][768], m = t*32+b
__device__ float g_H[2][2][HH * BB];                // [dir][buf][k*32+b]
__device__ int   g_bar[2 * SS];                     // per-step arrival counters
__device__ float g_scores[M16K];

// ---------------------------------- init ------------------------------------
__global__ void init_kernel() {
    int idx = blockIdx.x * blockDim.x + threadIdx.x;
    int nthr = gridDim.x * blockDim.x;
    float* h = &g_H[0][0][0];
    for (int i = idx; i < 2 * 2 * HH * BB; i += nthr) h[i] = 0.f;
    for (int i = idx; i < 2 * SS; i += nthr) g_bar[i] = 0;
    for (int i = idx; i < M16K; i += nthr) g_scores[i] = 0.f;
}

// ------------------------- input projection SGEMM ---------------------------
// C[n][m] = sum_k Wcat[n][k] * ip[b][t][k] + bias[n],  m = t*32+b
__global__ void __launch_bounds__(256) proj_gemm(
    const float* __restrict__ ip,
    const float* __restrict__ Wf, const float* __restrict__ Wb,
    const float* __restrict__ bf, const float* __restrict__ bbi)
{
    __shared__ float As[2][8][128];
    __shared__ float Bs[2][8][128];
    const int tid = threadIdx.x;
    const int n0 = blockIdx.y * 128;
    const int m0 = blockIdx.x * 128;
    const int tx = tid & 15, ty = tid >> 4;

    const int a_row = tid >> 1;
    const int a_col = (tid & 1) * 4;
    const int n_a = n0 + a_row;
    const float* Aptr = (n_a < G3) ? (Wf + (size_t)n_a * DD)
                                   : (Wb + (size_t)(n_a - G3) * DD);

    const int b_m = tid & 127;
    const int b_k = (tid >> 7) * 4;
    const int m = m0 + b_m;
    const float* Bptr = ip + ((size_t)(m & 31) * SS + (m >> 5)) * DD;

    float acc[8][8];
#pragma unroll
    for (int i = 0; i < 8; i++)
#pragma unroll
        for (int j = 0; j < 8; j++) acc[i][j] = 0.f;

    float4 aR = *(const float4*)(Aptr + a_col);
    float4 bR = *(const float4*)(Bptr + b_k);
    As[0][a_col + 0][a_row] = aR.x; As[0][a_col + 1][a_row] = aR.y;
    As[0][a_col + 2][a_row] = aR.z; As[0][a_col + 3][a_row] = aR.w;
    Bs[0][b_k + 0][b_m] = bR.x; Bs[0][b_k + 1][b_m] = bR.y;
    Bs[0][b_k + 2][b_m] = bR.z; Bs[0][b_k + 3][b_m] = bR.w;
    __syncthreads();

    const int KT = DD / 8;  // 96
    for (int kt = 0; kt < KT; ++kt) {
        int cur = kt & 1;
        if (kt < KT - 1) {
            aR = *(const float4*)(Aptr + (kt + 1) * 8 + a_col);
            bR = *(const float4*)(Bptr + (kt + 1) * 8 + b_k);
        }
#pragma unroll
        for (int kk = 0; kk < 8; ++kk) {
            float a0[8], b0[8];
            *(float4*)(a0)     = *(const float4*)&As[cur][kk][ty * 8];
            *(float4*)(a0 + 4) = *(const float4*)&As[cur][kk][ty * 8 + 4];
            *(float4*)(b0)     = *(const float4*)&Bs[cur][kk][tx * 8];
            *(float4*)(b0 + 4) = *(const float4*)&Bs[cur][kk][tx * 8 + 4];
#pragma unroll
            for (int i = 0; i < 8; i++)
#pragma unroll
                for (int j = 0; j < 8; j++)
                    acc[i][j] = fmaf(a0[i], b0[j], acc[i][j]);
        }
        if (kt < KT - 1) {
            int nx = cur ^ 1;
            As[nx][a_col + 0][a_row] = aR.x; As[nx][a_col + 1][a_row] = aR.y;
            As[nx][a_col + 2][a_row] = aR.z; As[nx][a_col + 3][a_row] = aR.w;
            Bs[nx][b_k + 0][b_m] = bR.x; Bs[nx][b_k + 1][b_m] = bR.y;
            Bs[nx][b_k + 2][b_m] = bR.z; Bs[nx][b_k + 3][b_m] = bR.w;
        }
        __syncthreads();
    }

#pragma unroll
    for (int i = 0; i < 8; i++) {
        int n = n0 + ty * 8 + i;
        float bv = (n < G3) ? bf[n] : bbi[n - G3];
        float4 o1 = make_float4(acc[i][0] + bv, acc[i][1] + bv,
                                acc[i][2] + bv, acc[i][3] + bv);
        float4 o2 = make_float4(acc[i][4] + bv, acc[i][5] + bv,
                                acc[i][6] + bv, acc[i][7] + bv);
        *(float4*)&g_XW[(size_t)n * M16K + m0 + tx * 8]     = o1;
        *(float4*)&g_XW[(size_t)n * M16K + m0 + tx * 8 + 4] = o2;
    }
}

// ---------------------------- GRU recurrence --------------------------------
// 128 CTAs: 64 per direction, each owns 6 hidden units for all 32 batches.
// SMEM layout (floats): Ws[3][6][384] | Hs[384][32] | xs[3][6][32] | bh[18] | Hn[6][32]
#define REC_THREADS 192
#define REC_SMEM_FLOATS (6912 + 12288 + 576 + 18 + 192)

__global__ void __launch_bounds__(REC_THREADS) gru_rec(
    const float* __restrict__ Whf, const float* __restrict__ Whb,
    const float* __restrict__ bhf, const float* __restrict__ bhb)
{
    extern __shared__ float sm[];
    float* Ws = sm;                 // 6912
    float* Hs = sm + 6912;          // 12288 (16B-aligned: 6912*4=27648)
    float* xs = sm + 19200;         // 576
    float* bh = sm + 19776;         // 18
    float* Hn = sm + 19794;         // 192

    const int bid = blockIdx.x;
    const int dir = bid >> 6;
    const int u0  = (bid & 63) * 6;
    const int tid = threadIdx.x;
    const int w = tid >> 5, lane = tid & 31;

    const float* Wh  = dir ? Whb : Whf;
    const float* bhh = dir ? bhb : bhf;

    // stationary weight slice: Ws[(g*6+u)*384+k] = W_hh[g*384 + u0+u][k]
    for (int idx = tid; idx < 18 * 384; idx += REC_THREADS) {
        int k = idx % 384;
        int ru = idx / 384;
        int g = ru / 6, u = ru % 6;
        Ws[idx] = Wh[((size_t)(g * 384 + u0 + u)) * 384 + k];
    }
    if (tid < 18) {
        int g = tid / 6, u = tid % 6;
        bh[tid] = bhh[g * 384 + u0 + u];
    }

    const float* wR = Ws + (0 * 6 + w) * 384;
    const float* wZ = Ws + (1 * 6 + w) * 384;
    const float* wN = Ws + (2 * 6 + w) * 384;
    const int j = u0 + w;

    int p = 0;
    for (int s = 0; s < SS; ++s) {
        const int t = dir ? (SS - 1 - s) : s;

        // stage H (L2-coherent loads, 48KB)
        {
            const float4* src = (const float4*)(&g_H[dir][p][0]);
            float4* dst = (float4*)Hs;
            for (int i = tid; i < (HH * BB) / 4; i += REC_THREADS)
                dst[i] = __ldcg(src + i);
        }
        // stage xw columns for this step: xs[(g*6+u)*32+b]
#pragma unroll
        for (int e = 0; e < 3; ++e) {
            int idx = e * REC_THREADS + tid;    // < 576
            int b = idx & 31;
            int ru = idx >> 5;
            int g = ru / 6, u = ru % 6;
            xs[idx] = g_XW[((size_t)(dir * G3 + g * 384 + u0 + u)) * M16K + t * 32 + b];
        }
        __syncthreads();

        float aR = bh[w], aZ = bh[6 + w], aN = bh[12 + w];
#pragma unroll 4
        for (int k4 = 0; k4 < 96; ++k4) {
            float4 r4 = *(const float4*)(wR + 4 * k4);
            float4 z4 = *(const float4*)(wZ + 4 * k4);
            float4 n4 = *(const float4*)(wN + 4 * k4);
            const float* hp = Hs + k4 * 128 + lane;
            float h0 = hp[0], h1 = hp[32], h2 = hp[64], h3 = hp[96];
            aR = fmaf(r4.x, h0, aR); aR = fmaf(r4.y, h1, aR);
            aR = fmaf(r4.z, h2, aR); aR = fmaf(r4.w, h3, aR);
            aZ = fmaf(z4.x, h0, aZ); aZ = fmaf(z4.y, h1, aZ);
            aZ = fmaf(z4.z, h2, aZ); aZ = fmaf(z4.w, h3, aZ);
            aN = fmaf(n4.x, h0, aN); aN = fmaf(n4.y, h1, aN);
            aN = fmaf(n4.z, h2, aN); aN = fmaf(n4.w, h3, aN);
        }

        float xr = xs[(0 * 6 + w) * 32 + lane];
        float xz = xs[(1 * 6 + w) * 32 + lane];
        float xn = xs[(2 * 6 + w) * 32 + lane];
        float r = 1.f / (1.f + expf(-(xr + aR)));
        float z = 1.f / (1.f + expf(-(xz + aZ)));
        float n = tanhf(xn + r * aN);
        float hold = Hs[j * 32 + lane];
        float hnew = n + z * (hold - n);

        __stcg(&g_H[dir][p ^ 1][j * 32 + lane], hnew);
        Hn[w * 32 + lane] = hnew;

        __threadfence();
        __syncthreads();

        // OUT write (transposed via smem for partial coalescing)
        {
            int b2 = tid / 6, jj = tid - b2 * 6;
            g_OUT[(size_t)(t * 32 + b2) * (2 * HH) + dir * HH + u0 + jj] = Hn[jj * 32 + b2];
        }

        // per-step inter-CTA barrier (64 CTAs per direction)
        if (tid == 0) {
            atomicAdd(&g_bar[dir * SS + s], 1);
            volatile int* bp = &g_bar[dir * SS + s];
            while (*bp < 64) { __nanosleep(32); }
            __threadfence();
        }
        __syncthreads();
        p ^= 1;
    }
}

// -------------------- attention scores GEMM (fused epilogue) ----------------
// scores[m] = sum_n tanh( OUT[m]·W_attn[n] + b_attn[n] ) * context[n]
__global__ void __launch_bounds__(256) attn_gemm(
    const float* __restrict__ Wa, const float* __restrict__ ba,
    const float* __restrict__ ctx)
{
    __shared__ float As[2][8][128];
    __shared__ float Bs[2][8][128];
    const int tid = threadIdx.x;
    const int m0 = blockIdx.x * 128;
    const int n0 = blockIdx.y * 128;
    const int tx = tid & 15, ty = tid >> 4;

    const int l_row = tid >> 1;
    const int l_col = (tid & 1) * 4;
    const float* Aptr = g_OUT + (size_t)(m0 + l_row) * (2 * HH);
    const float* Bptr = Wa + (size_t)(n0 + l_row) * (2 * HH);

    float acc[8][8];
#pragma unroll
    for (int i = 0; i < 8; i++)
#pragma unroll
        for (int j = 0; j < 8; j++) acc[i][j] = 0.f;

    float4 aR = *(const float4*)(Aptr + l_col);
    float4 bR = *(const float4*)(Bptr + l_col);
    As[0][l_col + 0][l_row] = aR.x; As[0][l_col + 1][l_row] = aR.y;
    As[0][l_col + 2][l_row] = aR.z; As[0][l_col + 3][l_row] = aR.w;
    Bs[0][l_col + 0][l_row] = bR.x; Bs[0][l_col + 1][l_row] = bR.y;
    Bs[0][l_col + 2][l_row] = bR.z; Bs[0][l_col + 3][l_row] = bR.w;
    __syncthreads();

    const int KT = (2 * HH) / 8;  // 96
    for (int kt = 0; kt < KT; ++kt) {
        int cur = kt & 1;
        if (kt < KT - 1) {
            aR = *(const float4*)(Aptr + (kt + 1) * 8 + l_col);
            bR = *(const float4*)(Bptr + (kt + 1) * 8 + l_col);
        }
#pragma unroll
        for (int kk = 0; kk < 8; ++kk) {
            float a0[8], b0[8];
            *(float4*)(a0)     = *(const float4*)&As[cur][kk][ty * 8];
            *(float4*)(a0 + 4) = *(const float4*)&As[cur][kk][ty * 8 + 4];
            *(float4*)(b0)     = *(const float4*)&Bs[cur][kk][tx * 8];
            *(float4*)(b0 + 4) = *(const float4*)&Bs[cur][kk][tx * 8 + 4];
#pragma unroll
            for (int i = 0; i < 8; i++)
#pragma unroll
                for (int j = 0; j < 8; j++)
                    acc[i][j] = fmaf(a0[i], b0[j], acc[i][j]);
        }
        if (kt < KT - 1) {
            int nx = cur ^ 1;
            As[nx][l_col + 0][l_row] = aR.x; As[nx][l_col + 1][l_row] = aR.y;
            As[nx][l_col + 2][l_row] = aR.z; As[nx][l_col + 3][l_row] = aR.w;
            Bs[nx][l_col + 0][l_row] = bR.x; Bs[nx][l_col + 1][l_row] = bR.y;
            Bs[nx][l_col + 2][l_row] = bR.z; Bs[nx][l_col + 3][l_row] = bR.w;
        }
        __syncthreads();
    }

#pragma unroll
    for (int i = 0; i < 8; i++) {
        float partial = 0.f;
#pragma unroll
        for (int jj = 0; jj < 8; jj++) {
            int n = n0 + tx * 8 + jj;
            partial += tanhf(acc[i][jj] + ba[n]) * ctx[n];
        }
        atomicAdd(&g_scores[m0 + ty * 8 + i], partial);
    }
}

// ------------------------- softmax + attention pooling ----------------------
__global__ void __launch_bounds__(256) attn_pool(float* __restrict__ out)
{
    __shared__ float sc[SS];
    __shared__ float red[256];
    const int b = blockIdx.x;
    const int tid = threadIdx.x;

    for (int t = tid; t < SS; t += 256) sc[t] = g_scores[t * 32 + b];
    __syncthreads();

    float mx = -3.4e38f;
    for (int t = tid; t < SS; t += 256) mx = fmaxf(mx, sc[t]);
    red[tid] = mx;
    __syncthreads();
    for (int sft = 128; sft > 0; sft >>= 1) {
        if (tid < sft) red[tid] = fmaxf(red[tid], red[tid + sft]);
        __syncthreads();
    }
    mx = red[0];
    __syncthreads();

    float lsum = 0.f;
    for (int t = tid; t < SS; t += 256) {
        float e = expf(sc[t] - mx);
        sc[t] = e;
        lsum += e;
    }
    red[tid] = lsum;
    __syncthreads();
    for (int sft = 128; sft > 0; sft >>= 1) {
        if (tid < sft) red[tid] += red[tid + sft];
        __syncthreads();
    }
    float inv = 1.f / red[0];
    __syncthreads();

#pragma unroll
    for (int pass = 0; pass < 3; ++pass) {
        int dd = pass * 256 + tid;
        float acc = 0.f;
#pragma unroll 4
        for (int t = 0; t < SS; ++t)
            acc = fmaf(sc[t], g_OUT[(size_t)(t * 32 + b) * (2 * HH) + dd], acc);
        out[b * (2 * HH) + dd] = acc * inv;
    }
}

// --------------------------------- launch -----------------------------------
extern "C" void kernel_launch(void* const* d_in, const int* in_sizes, int n_in,
                              void* d_out, int out_size)
{
    const float* ip   = (const float*)d_in[0];
    const float* Wihf = (const float*)d_in[1];
    const float* Whhf = (const float*)d_in[2];
    const float* bihf = (const float*)d_in[3];
    const float* bhhf = (const float*)d_in[4];
    const float* Wihb = (const float*)d_in[5];
    const float* Whhb = (const float*)d_in[6];
    const float* bihb = (const float*)d_in[7];
    const float* bhhb = (const float*)d_in[8];
    const float* Wa   = (const float*)d_in[9];
    const float* ba   = (const float*)d_in[10];
    const float* ctx  = (const float*)d_in[11];
    float* out = (float*)d_out;

    const int rec_smem = REC_SMEM_FLOATS * 4;  // 79944 bytes
    cudaFuncSetAttribute(gru_rec, cudaFuncAttributeMaxDynamicSharedMemorySize, rec_smem);

    init_kernel<<<64, 256>>>();
    proj_gemm<<<dim3(M16K / 128, NROWS / 128), 256>>>(ip, Wihf, Wihb, bihf, bihb);
    gru_rec<<<128, REC_THREADS, rec_smem>>>(Whhf, Whhb, bhhf, bhhb);
    attn_gemm<<<dim3(M16K / 128, (2 * HH) / 128), 256>>>(Wa, ba, ctx);
    attn_pool<<<32, 256>>>(out);
}

// round 3
// speedup vs baseline: 1.1645x; 1.1645x over previous
#include <cuda_runtime.h>
#include <cuda_fp16.h>
#include <math.h>
#include <stdint.h>

#define BB   32
#define SS   512
#define DD   768
#define HH   384
#define G3   (3*HH)      // 1152
#define NROWS (2*G3)     // 2304
#define M16K (SS*BB)     // 16384
#define KC   (3*DD)      // 2304  (split-concat K)

// ---------------- scratch (static device globals; no runtime alloc) ----------
__device__ float g_XW[(size_t)NROWS * M16K];        // [n][m], m = t*32+b
__device__ float g_OUT[(size_t)M16K * (2*HH)];      // [m][768]
__device__ float g_H[2][2][HH * BB];                // [dir][buf][k*32+b]
__device__ int   g_bar[2 * SS];
__device__ float g_scores[M16K];
// fp16 split-concat operands: A = [Wh | Wh | Wl], B = [Xh | Xl | Xh]
__device__ __half g_Ac[(size_t)NROWS * KC];         // [n][2304]
__device__ __half g_Bc[(size_t)M16K  * KC];         // [m][2304]

// ============================ PTX helpers (sm_80-safe) =======================
__device__ __forceinline__ uint32_t smem_u32(const void* p) {
    uint32_t a;
    asm("{ .reg .u64 t; cvta.to.shared.u64 t, %1; cvt.u32.u64 %0, t; }"
        : "=r"(a) : "l"(p));
    return a;
}

#define CP_ASYNC16(saddr, gptr) \
    asm volatile("cp.async.cg.shared.global [%0], [%1], 16;" \
                 :: "r"(saddr), "l"(gptr) : "memory")
#define CP_COMMIT() asm volatile("cp.async.commit_group;" ::: "memory")
#define CP_WAIT2()  asm volatile("cp.async.wait_group 2;" ::: "memory")

#define LDMATRIX_X4(r0, r1, r2, r3, addr) \
    asm volatile("ldmatrix.sync.aligned.m8n8.x4.shared.b16 {%0,%1,%2,%3}, [%4];" \
                 : "=r"(r0), "=r"(r1), "=r"(r2), "=r"(r3) : "r"(addr))

#define MMA16816(c0, c1, c2, c3, a0, a1, a2, a3, b0, b1) \
    asm volatile("mma.sync.aligned.m16n8k16.row.col.f32.f16.f16.f32 " \
                 "{%0,%1,%2,%3}, {%4,%5,%6,%7}, {%8,%9}, {%0,%1,%2,%3};" \
                 : "+f"(c0), "+f"(c1), "+f"(c2), "+f"(c3) \
                 : "r"(a0), "r"(a1), "r"(a2), "r"(a3), "r"(b0), "r"(b1))

// ---------------------------------- init ------------------------------------
__global__ void init_kernel() {
    int idx = blockIdx.x * blockDim.x + threadIdx.x;
    int nthr = gridDim.x * blockDim.x;
    float* h = &g_H[0][0][0];
    for (int i = idx; i < 2 * 2 * HH * BB; i += nthr) h[i] = 0.f;
    for (int i = idx; i < 2 * SS; i += nthr) g_bar[i] = 0;
    for (int i = idx; i < M16K; i += nthr) g_scores[i] = 0.f;
}

// ---------------- fp32 -> fp16 hi/lo split + K-concat conversion -------------
// B rows 0..16383: X (ip reordered, m = t*32+b), segs [h | l | h]
// A rows 0..2303 : Wcat,                         segs [h | h | l]
__global__ void __launch_bounds__(256) convert_split(
    const float* __restrict__ ip,
    const float* __restrict__ Wf, const float* __restrict__ Wb)
{
    const int TOT = (M16K + NROWS) * (DD / 4);
    int idx = blockIdx.x * blockDim.x + threadIdx.x;
    if (idx >= TOT) return;
    int row = idx / (DD / 4);
    int k = (idx - row * (DD / 4)) * 4;

    const float* src;
    __half* dst;    // row base in concat buffer
    bool isA;
    if (row < M16K) {
        int b = row & 31, t = row >> 5;
        src = ip + ((size_t)(b * SS + t)) * DD + k;
        dst = g_Bc + (size_t)row * KC;
        isA = false;
    } else {
        int n = row - M16K;
        src = ((n < G3) ? (Wf + (size_t)n * DD) : (Wb + (size_t)(n - G3) * DD)) + k;
        dst = g_Ac + (size_t)n * KC;
        isA = true;
    }
    float4 v = *(const float4*)src;
    union { __half h[4]; uint2 u; } hi, lo;
    hi.h[0] = __float2half_rn(v.x); lo.h[0] = __float2half_rn(v.x - __half2float(hi.h[0]));
    hi.h[1] = __float2half_rn(v.y); lo.h[1] = __float2half_rn(v.y - __half2float(hi.h[1]));
    hi.h[2] = __float2half_rn(v.z); lo.h[2] = __float2half_rn(v.z - __half2float(hi.h[2]));
    hi.h[3] = __float2half_rn(v.w); lo.h[3] = __float2half_rn(v.w - __half2float(hi.h[3]));

    if (isA) {   // [h | h | l]
        *(uint2*)(dst + k)            = hi.u;
        *(uint2*)(dst + DD + k)       = hi.u;
        *(uint2*)(dst + 2 * DD + k)   = lo.u;
    } else {     // [h | l | h]
        *(uint2*)(dst + k)            = hi.u;
        *(uint2*)(dst + DD + k)       = lo.u;
        *(uint2*)(dst + 2 * DD + k)   = hi.u;
    }
}

// --------------------- HGEMM input projection (mma.sync) ---------------------
// C[n 128][m 128] = A[n][K=2304] * B[m][K]^T, fp16 operands, fp32 accum.
// 8 warps = 2(n) x 4(m), warp tile 64x32. 4-stage cp.async pipeline.
// smem rows padded to 40 halves (80B) -> ldmatrix conflict-free.
#define PROJ_STAGE_BYTES 10240          // 128 rows * 80B
#define PROJ_DYN_SMEM    (8 * PROJ_STAGE_BYTES)   // 4 stages x (A+B) = 81920

__global__ void __launch_bounds__(256, 2) proj_hgemm(
    const float* __restrict__ bihf, const float* __restrict__ bihb)
{
    extern __shared__ char dyn[];
    const uint32_t Abase = smem_u32(dyn);
    const uint32_t Bbase = Abase + 4 * PROJ_STAGE_BYTES;

    const int tid  = threadIdx.x;
    const int wid  = tid >> 5, lane = tid & 31;
    const int wn   = wid >> 2;            // 0..1
    const int wm   = wid & 3;             // 0..3
    const int n0   = blockIdx.x * 128;    // x = n (fast) for L2 reuse of A
    const int m0   = blockIdx.y * 128;

    const int KT = KC / 32;               // 72

    // ---- async loader for one stage
    auto load_stage = [&](int buf, int kt) {
        uint32_t as = Abase + buf * PROJ_STAGE_BYTES;
        uint32_t bs = Bbase + buf * PROJ_STAGE_BYTES;
#pragma unroll
        for (int i = 0; i < 2; ++i) {
            int idx = tid + i * 256;           // 0..511
            int row = idx >> 2, c = idx & 3;
            const __half* ga = g_Ac + (size_t)(n0 + row) * KC + kt * 32 + c * 8;
            CP_ASYNC16(as + row * 80 + c * 16, ga);
            const __half* gb = g_Bc + (size_t)(m0 + row) * KC + kt * 32 + c * 8;
            CP_ASYNC16(bs + row * 80 + c * 16, gb);
        }
        CP_COMMIT();
    };

    float acc[4][4][4];
#pragma unroll
    for (int i = 0; i < 4; i++)
#pragma unroll
        for (int j = 0; j < 4; j++)
#pragma unroll
            for (int r = 0; r < 4; r++) acc[i][j][r] = 0.f;

    load_stage(0, 0);
    load_stage(1, 1);
    load_stage(2, 2);

    const int lr = lane & 15;
    const int lc = lane >> 4;

    for (int kt = 0; kt < KT; ++kt) {
        CP_WAIT2();
        __syncthreads();
        if (kt + 3 < KT) load_stage((kt + 3) & 3, kt + 3);
        else CP_COMMIT();                      // keep group count advancing

        uint32_t as = Abase + (kt & 3) * PROJ_STAGE_BYTES;
        uint32_t bs = Bbase + (kt & 3) * PROJ_STAGE_BYTES;

#pragma unroll
        for (int kk = 0; kk < 2; ++kk) {
            // B fragments for this warp's 32 m-cols
            uint32_t bfr[4][2];
#pragma unroll
            for (int bm = 0; bm < 2; ++bm) {
                uint32_t r0, r1, r2, r3;
                uint32_t addr = bs + (wm * 32 + bm * 16 + lr) * 80 + (kk * 2 + lc) * 16;
                LDMATRIX_X4(r0, r1, r2, r3, addr);
                bfr[bm * 2 + 0][0] = r0; bfr[bm * 2 + 0][1] = r2;
                bfr[bm * 2 + 1][0] = r1; bfr[bm * 2 + 1][1] = r3;
            }
#pragma unroll
            for (int fn = 0; fn < 4; ++fn) {
                uint32_t a0, a1, a2, a3;
                uint32_t addr = as + (wn * 64 + fn * 16 + lr) * 80 + (kk * 2 + lc) * 16;
                LDMATRIX_X4(a0, a1, a2, a3, addr);
#pragma unroll
                for (int fm = 0; fm < 4; ++fm) {
                    MMA16816(acc[fn][fm][0], acc[fn][fm][1], acc[fn][fm][2], acc[fn][fm][3],
                             a0, a1, a2, a3, bfr[fm][0], bfr[fm][1]);
                }
            }
        }
        __syncthreads();
    }

    // ---- epilogue: stage C through smem for coalesced global stores ----
    float* Cs = (float*)dyn;                 // [128][136]
    const int crow = lane >> 2;
    const int ccol = 2 * (lane & 3);
#pragma unroll
    for (int fn = 0; fn < 4; ++fn) {
#pragma unroll
        for (int fm = 0; fm < 4; ++fm) {
            int r = wn * 64 + fn * 16 + crow;
            int c = wm * 32 + fm * 8 + ccol;
            Cs[r * 136 + c]             = acc[fn][fm][0];
            Cs[r * 136 + c + 1]         = acc[fn][fm][1];
            Cs[(r + 8) * 136 + c]       = acc[fn][fm][2];
            Cs[(r + 8) * 136 + c + 1]   = acc[fn][fm][3];
        }
    }
    __syncthreads();

#pragma unroll
    for (int it = 0; it < 16; ++it) {
        int idx = tid + it * 256;            // 0..4095 float4 slots
        int row = idx >> 5, cq = idx & 31;
        int n = n0 + row;
        float bv = (n < G3) ? __ldg(bihf + n) : __ldg(bihb + n - G3);
        float4 v;
        v.x = Cs[row * 136 + cq * 4 + 0] + bv;
        v.y = Cs[row * 136 + cq * 4 + 1] + bv;
        v.z = Cs[row * 136 + cq * 4 + 2] + bv;
        v.w = Cs[row * 136 + cq * 4 + 3] + bv;
        *(float4*)&g_XW[(size_t)n * M16K + m0 + cq * 4] = v;
    }
}

// ---------------------------- GRU recurrence --------------------------------
#define REC_THREADS 192
#define REC_SMEM_FLOATS (6912 + 12288 + 576 + 18 + 192)

__global__ void __launch_bounds__(REC_THREADS) gru_rec(
    const float* __restrict__ Whf, const float* __restrict__ Whb,
    const float* __restrict__ bhf, const float* __restrict__ bhb)
{
    extern __shared__ float sm[];
    float* Ws = sm;
    float* Hs = sm + 6912;
    float* xs = sm + 19200;
    float* bh = sm + 19776;
    float* Hn = sm + 19794;

    const int bid = blockIdx.x;
    const int dir = bid >> 6;
    const int u0  = (bid & 63) * 6;
    const int tid = threadIdx.x;
    const int w = tid >> 5, lane = tid & 31;

    const float* Wh  = dir ? Whb : Whf;
    const float* bhh = dir ? bhb : bhf;

    for (int idx = tid; idx < 18 * 384; idx += REC_THREADS) {
        int k = idx % 384;
        int ru = idx / 384;
        int g = ru / 6, u = ru % 6;
        Ws[idx] = Wh[((size_t)(g * 384 + u0 + u)) * 384 + k];
    }
    if (tid < 18) {
        int g = tid / 6, u = tid % 6;
        bh[tid] = bhh[g * 384 + u0 + u];
    }

    const float* wR = Ws + (0 * 6 + w) * 384;
    const float* wZ = Ws + (1 * 6 + w) * 384;
    const float* wN = Ws + (2 * 6 + w) * 384;
    const int j = u0 + w;

    int p = 0;
    for (int s = 0; s < SS; ++s) {
        const int t = dir ? (SS - 1 - s) : s;
        {
            const float4* src = (const float4*)(&g_H[dir][p][0]);
            float4* dst = (float4*)Hs;
            for (int i = tid; i < (HH * BB) / 4; i += REC_THREADS)
                dst[i] = __ldcg(src + i);
        }
#pragma unroll
        for (int e = 0; e < 3; ++e) {
            int idx = e * REC_THREADS + tid;
            int b = idx & 31;
            int ru = idx >> 5;
            int g = ru / 6, u = ru % 6;
            xs[idx] = g_XW[((size_t)(dir * G3 + g * 384 + u0 + u)) * M16K + t * 32 + b];
        }
        __syncthreads();

        float aR = bh[w], aZ = bh[6 + w], aN = bh[12 + w];
#pragma unroll 4
        for (int k4 = 0; k4 < 96; ++k4) {
            float4 r4 = *(const float4*)(wR + 4 * k4);
            float4 z4 = *(const float4*)(wZ + 4 * k4);
            float4 n4 = *(const float4*)(wN + 4 * k4);
            const float* hp = Hs + k4 * 128 + lane;
            float h0 = hp[0], h1 = hp[32], h2 = hp[64], h3 = hp[96];
            aR = fmaf(r4.x, h0, aR); aR = fmaf(r4.y, h1, aR);
            aR = fmaf(r4.z, h2, aR); aR = fmaf(r4.w, h3, aR);
            aZ = fmaf(z4.x, h0, aZ); aZ = fmaf(z4.y, h1, aZ);
            aZ = fmaf(z4.z, h2, aZ); aZ = fmaf(z4.w, h3, aZ);
            aN = fmaf(n4.x, h0, aN); aN = fmaf(n4.y, h1, aN);
            aN = fmaf(n4.z, h2, aN); aN = fmaf(n4.w, h3, aN);
        }

        float xr = xs[(0 * 6 + w) * 32 + lane];
        float xz = xs[(1 * 6 + w) * 32 + lane];
        float xn = xs[(2 * 6 + w) * 32 + lane];
        float r = 1.f / (1.f + expf(-(xr + aR)));
        float z = 1.f / (1.f + expf(-(xz + aZ)));
        float n = tanhf(xn + r * aN);
        float hold = Hs[j * 32 + lane];
        float hnew = n + z * (hold - n);

        __stcg(&g_H[dir][p ^ 1][j * 32 + lane], hnew);
        Hn[w * 32 + lane] = hnew;

        __threadfence();
        __syncthreads();

        {
            int b2 = tid / 6, jj = tid - b2 * 6;
            g_OUT[(size_t)(t * 32 + b2) * (2 * HH) + dir * HH + u0 + jj] = Hn[jj * 32 + b2];
        }

        if (tid == 0) {
            atomicAdd(&g_bar[dir * SS + s], 1);
            volatile int* bp = &g_bar[dir * SS + s];
            while (*bp < 64) { __nanosleep(32); }
            __threadfence();
        }
        __syncthreads();
        p ^= 1;
    }
}

// -------------------- attention scores GEMM (fused epilogue) ----------------
__global__ void __launch_bounds__(256) attn_gemm(
    const float* __restrict__ Wa, const float* __restrict__ ba,
    const float* __restrict__ ctx)
{
    __shared__ float As[2][8][128];
    __shared__ float Bs[2][8][128];
    const int tid = threadIdx.x;
    const int m0 = blockIdx.x * 128;
    const int n0 = blockIdx.y * 128;
    const int tx = tid & 15, ty = tid >> 4;

    const int l_row = tid >> 1;
    const int l_col = (tid & 1) * 4;
    const float* Aptr = g_OUT + (size_t)(m0 + l_row) * (2 * HH);
    const float* Bptr = Wa + (size_t)(n0 + l_row) * (2 * HH);

    float acc[8][8];
#pragma unroll
    for (int i = 0; i < 8; i++)
#pragma unroll
        for (int jj = 0; jj < 8; jj++) acc[i][jj] = 0.f;

    float4 aR = *(const float4*)(Aptr + l_col);
    float4 bR = *(const float4*)(Bptr + l_col);
    As[0][l_col + 0][l_row] = aR.x; As[0][l_col + 1][l_row] = aR.y;
    As[0][l_col + 2][l_row] = aR.z; As[0][l_col + 3][l_row] = aR.w;
    Bs[0][l_col + 0][l_row] = bR.x; Bs[0][l_col + 1][l_row] = bR.y;
    Bs[0][l_col + 2][l_row] = bR.z; Bs[0][l_col + 3][l_row] = bR.w;
    __syncthreads();

    const int KT = (2 * HH) / 8;
    for (int kt = 0; kt < KT; ++kt) {
        int cur = kt & 1;
        if (kt < KT - 1) {
            aR = *(const float4*)(Aptr + (kt + 1) * 8 + l_col);
            bR = *(const float4*)(Bptr + (kt + 1) * 8 + l_col);
        }
#pragma unroll
        for (int kk = 0; kk < 8; ++kk) {
            float a0[8], b0[8];
            *(float4*)(a0)     = *(const float4*)&As[cur][kk][ty * 8];
            *(float4*)(a0 + 4) = *(const float4*)&As[cur][kk][ty * 8 + 4];
            *(float4*)(b0)     = *(const float4*)&Bs[cur][kk][tx * 8];
            *(float4*)(b0 + 4) = *(const float4*)&Bs[cur][kk][tx * 8 + 4];
#pragma unroll
            for (int i = 0; i < 8; i++)
#pragma unroll
                for (int jj = 0; jj < 8; jj++)
                    acc[i][jj] = fmaf(a0[i], b0[jj], acc[i][jj]);
        }
        if (kt < KT - 1) {
            int nx = cur ^ 1;
            As[nx][l_col + 0][l_row] = aR.x; As[nx][l_col + 1][l_row] = aR.y;
            As[nx][l_col + 2][l_row] = aR.z; As[nx][l_col + 3][l_row] = aR.w;
            Bs[nx][l_col + 0][l_row] = bR.x; Bs[nx][l_col + 1][l_row] = bR.y;
            Bs[nx][l_col + 2][l_row] = bR.z; Bs[nx][l_col + 3][l_row] = bR.w;
        }
        __syncthreads();
    }

#pragma unroll
    for (int i = 0; i < 8; i++) {
        float partial = 0.f;
#pragma unroll
        for (int jj = 0; jj < 8; jj++) {
            int n = n0 + tx * 8 + jj;
            partial += tanhf(acc[i][jj] + ba[n]) * ctx[n];
        }
        atomicAdd(&g_scores[m0 + ty * 8 + i], partial);
    }
}

// ------------------------- softmax + attention pooling ----------------------
__global__ void __launch_bounds__(256) attn_pool(float* __restrict__ out)
{
    __shared__ float sc[SS];
    __shared__ float red[256];
    const int b = blockIdx.x;
    const int tid = threadIdx.x;

    for (int t = tid; t < SS; t += 256) sc[t] = g_scores[t * 32 + b];
    __syncthreads();

    float mx = -3.4e38f;
    for (int t = tid; t < SS; t += 256) mx = fmaxf(mx, sc[t]);
    red[tid] = mx;
    __syncthreads();
    for (int sft = 128; sft > 0; sft >>= 1) {
        if (tid < sft) red[tid] = fmaxf(red[tid], red[tid + sft]);
        __syncthreads();
    }
    mx = red[0];
    __syncthreads();

    float lsum = 0.f;
    for (int t = tid; t < SS; t += 256) {
        float e = expf(sc[t] - mx);
        sc[t] = e;
        lsum += e;
    }
    red[tid] = lsum;
    __syncthreads();
    for (int sft = 128; sft > 0; sft >>= 1) {
        if (tid < sft) red[tid] += red[tid + sft];
        __syncthreads();
    }
    float inv = 1.f / red[0];
    __syncthreads();

#pragma unroll
    for (int pass = 0; pass < 3; ++pass) {
        int dd = pass * 256 + tid;
        float acc = 0.f;
#pragma unroll 4
        for (int t = 0; t < SS; ++t)
            acc = fmaf(sc[t], g_OUT[(size_t)(t * 32 + b) * (2 * HH) + dd], acc);
        out[b * (2 * HH) + dd] = acc * inv;
    }
}

// --------------------------------- launch -----------------------------------
extern "C" void kernel_launch(void* const* d_in, const int* in_sizes, int n_in,
                              void* d_out, int out_size)
{
    const float* ip   = (const float*)d_in[0];
    const float* Wihf = (const float*)d_in[1];
    const float* Whhf = (const float*)d_in[2];
    const float* bihf = (const float*)d_in[3];
    const float* bhhf = (const float*)d_in[4];
    const float* Wihb = (const float*)d_in[5];
    const float* Whhb = (const float*)d_in[6];
    const float* bihb = (const float*)d_in[7];
    const float* bhhb = (const float*)d_in[8];
    const float* Wa   = (const float*)d_in[9];
    const float* ba   = (const float*)d_in[10];
    const float* ctx  = (const float*)d_in[11];
    float* out = (float*)d_out;

    const int rec_smem = REC_SMEM_FLOATS * 4;
    cudaFuncSetAttribute(gru_rec, cudaFuncAttributeMaxDynamicSharedMemorySize, rec_smem);
    cudaFuncSetAttribute(proj_hgemm, cudaFuncAttributeMaxDynamicSharedMemorySize, PROJ_DYN_SMEM);

    init_kernel<<<64, 256>>>();
    {
        int tot = (M16K + NROWS) * (DD / 4);
        convert_split<<<(tot + 255) / 256, 256>>>(ip, Wihf, Wihb);
    }
    proj_hgemm<<<dim3(NROWS / 128, M16K / 128), 256, PROJ_DYN_SMEM>>>(bihf, bihb);
    gru_rec<<<128, REC_THREADS, rec_smem>>>(Whhf, Whhb, bhhf, bhhb);
    attn_gemm<<<dim3(M16K / 128, (2 * HH) / 128), 256>>>(Wa, ba, ctx);
    attn_pool<<<32, 256>>>(out);
}